// round 14
// baseline (speedup 1.0000x reference)
#include <cuda_runtime.h>
#include <cstdint>

#define NEG_INF  (-1e8f)
#define M_EMPTY  (-1e30f)
#define INVLN2 1.4426950408889634f
#define LN2    0.6931471805599453f

__device__ __forceinline__ float ex2f(float x){ float r; asm("ex2.approx.ftz.f32 %0, %1;" : "=f"(r) : "f"(x)); return r; }
__device__ __forceinline__ float lg2f(float x){ float r; asm("lg2.approx.ftz.f32 %0, %1;" : "=f"(r) : "f"(x)); return r; }

__device__ __forceinline__ float lse2(float a, float b){
    float m = fmaxf(a, b);
    return m + lg2f(1.0f + ex2f(-fabsf(a - b)));
}
__device__ __forceinline__ float lse3(float a, float b, float c){
    float m = fmaxf(fmaxf(a, b), c);
    return m + lg2f(ex2f(a - m) + ex2f(b - m) + ex2f(c - m));
}
// online-softmax fold, identity (M_EMPTY, 0); branch-free
__device__ __forceinline__ void mqcomb(float& M, float& Q, float Ma, float Qa){
    float f  = ex2f(-fabsf(M - Ma));
    bool  ge = (M >= Ma);
    float q1 = fmaf(Qa, f, Q);
    float q2 = fmaf(Q,  f, Qa);
    Q = ge ? q1 : q2;
    M = fmaxf(M, Ma);
}
__device__ __forceinline__ void st_release_s32(uint32_t saddr, int v){
    asm volatile("st.release.cta.shared::cta.u32 [%0], %1;" :: "r"(saddr), "r"(v) : "memory");
}
__device__ __forceinline__ int ld_acquire_s32(uint32_t saddr){
    int v;
    asm volatile("ld.acquire.cta.shared::cta.u32 %0, [%1];" : "=r"(v) : "r"(saddr) : "memory");
    return v;
}
__device__ __forceinline__ uint32_t smem_u32(const void* p){
    return (uint32_t)__cvta_generic_to_shared(p);
}

struct Row { float t0,t1,t2,a0,a1,a2,a3,a4,a5,a6,a7,a8; };

// One CTA (8 warps) per batch; warp w = pipeline stage owning cols [32w,32w+32),
// one column per lane. Log2-domain DP with S/T factorization + MQ online-softmax
// scan; late-fold head pairs (P computed in previous row's tail). Inter-warp
// edge carry (u0,u1,x at col 32w+31) via smem ring + acquire/release flags.
// Two stage-warps per SMSP interleave to hide dependency-chain stalls.
__global__ __launch_bounds__(256, 1)
void forward_decoder_kernel(const float* __restrict__ theta,
                            const float* __restrict__ A,
                            float* __restrict__ out){
    constexpr int N = 256;
    const int lane = threadIdx.x & 31;
    const int w    = threadIdx.x >> 5;      // stage 0..7
    const int b    = blockIdx.x;
    const int jc   = (w << 5) + lane;       // column 0..255

    __shared__ float4  pay[8][8];
    __shared__ uint32_t flag[8];
    __shared__ uint32_t ack[8];
    if(threadIdx.x < 8){ flag[threadIdx.x] = 0; ack[threadIdx.x] = 0; }
    __syncthreads();   // only CTA barrier

    const uint32_t flag_prev = smem_u32(&flag[(w + 7) & 7]);
    const uint32_t flag_own  = smem_u32(&flag[w]);
    const uint32_t ack_own   = smem_u32(&ack[w]);
    const uint32_t ack_next  = smem_u32(&ack[(w + 1) & 7]);

    // parity-aligned load bases: load even-word-aligned float2s covering the
    // needed 3 (theta) / 9 (A) words, then parity-select. 36B/12B strides have
    // no uniform 8B alignment per column; this keeps all LDGs 8B-aligned.
    const int tW = jc * 3;  const bool to = (tW & 1);
    const int aW = jc * 9;  const bool ao = (aW & 1);
    const float* thb = theta + (size_t)b * 196608 + (tW & ~1);
    const float* Ab  = A     + (size_t)b * 589824 + (aW & ~1);

    auto loadrow = [&](int r, Row& d){
        const float2* tp = (const float2*)(thb + (size_t)r * 768);
        const float2* ap = (const float2*)(Ab  + (size_t)r * 2304);
        float2 q0 = __ldg(tp), q1 = __ldg(tp + 1);
        float2 r0 = __ldg(ap),     r1 = __ldg(ap + 1), r2 = __ldg(ap + 2),
               r3 = __ldg(ap + 3), r4 = __ldg(ap + 4);
        d.t0 = to ? q0.y : q0.x;  d.t1 = to ? q1.x : q0.y;  d.t2 = to ? q1.y : q1.x;
        d.a0 = ao ? r0.y : r0.x;  d.a1 = ao ? r1.x : r0.y;  d.a2 = ao ? r1.y : r1.x;
        d.a3 = ao ? r2.x : r1.y;  d.a4 = ao ? r2.y : r2.x;  d.a5 = ao ? r3.x : r2.y;
        d.a6 = ao ? r3.y : r3.x;  d.a7 = ao ? r4.x : r3.y;  d.a8 = ao ? r4.y : r4.x;
    };

    Row cur, nxA, nxB;
    loadrow(0, cur);
    loadrow(1, nxA);

    // prologue: row-0 head pairs from boundary V (V[0,0]=0, rest NEG_INF)
    float bv = (w == 0 && lane == 0) ? 0.0f : NEG_INF;
    float P0 = lse2(fmaf(cur.a0, INVLN2, bv),      fmaf(cur.a1, INVLN2, bv));
    float P1 = lse2(fmaf(cur.a3, INVLN2, NEG_INF), fmaf(cur.a4, INVLN2, NEG_INF));
    float dlate = bv;
    float pv2 = NEG_INF;
    float u0 = NEG_INF, u1 = NEG_INF, x = NEG_INF;
    float u0in = NEG_INF, u1in = NEG_INF, xin = NEG_INF;

    auto body = [&](int r, Row& nx, Row& ld){
        // prefetch row r+2 (consumed at NEXT iter's tail: ~1.5 periods away)
        if(r + 2 < N) loadrow(r + 2, ld);

        // heads: single lse2 fold with late V2 terms (on x-chain)
        u0 = fmaf(cur.t0, INVLN2, lse2(P0, fmaf(cur.a2, INVLN2, dlate)));
        u1 = fmaf(cur.t1, INVLN2, lse2(P1, fmaf(cur.a5, INVLN2, pv2)));

        float num0 = __shfl_up_sync(0xffffffffu, u0, 1);
        float num1 = __shfl_up_sync(0xffffffffu, u1, 1);

        float t2l = cur.t2 * INVLN2;
        float a   = fmaf(cur.a8, INVLN2, t2l);

        // edge carry from stage w-1 (hoisted early: z-prep runs parallel to scans)
        if(w > 0){
            while(ld_acquire_s32(flag_prev) < r + 1){ }
            float4 ps = pay[w-1][r & 7];
            u0in = ps.x; u1in = ps.y; xin = ps.z;
            if(lane == 0) st_release_s32(ack_own, r + 1);
        }
        // lane-0 deferred element: c0 - S0 (valid on lane 0), broadcast
        float c0 = t2l + lse2(fmaf(cur.a6, INVLN2, u0in), fmaf(cur.a7, INVLN2, u1in));
        float cb = __shfl_sync(0xffffffffu, c0 - a, 0);
        float zM = fmaxf(xin, cb);
        float zQ = 1.0f + ex2f(-fabsf(xin - cb));

        // FADD prefix-sum of a (off-chain)
        float S = a;
        #pragma unroll
        for(int dlt = 1; dlt < 32; dlt <<= 1){
            float v = __shfl_up_sync(0xffffffffu, S, dlt);
            S += (lane >= dlt) ? v : 0.0f;
        }

        float c = t2l + lse2(fmaf(cur.a6, INVLN2, num0), fmaf(cur.a7, INVLN2, num1));
        float T = c - S;
        float Mi = (lane == 0) ? M_EMPTY : T;
        float Qi = (lane == 0) ? 0.0f    : 1.0f;

        // inclusive MQ Kogge-Stone (identity-masked, branch-free)
        #pragma unroll
        for(int dlt = 1; dlt < 32; dlt <<= 1){
            float Mn = __shfl_up_sync(0xffffffffu, Mi, dlt);
            float Qn = __shfl_up_sync(0xffffffffu, Qi, dlt);
            bool take = (lane >= dlt);
            Mn = take ? Mn : M_EMPTY;
            Qn = take ? Qn : 0.0f;
            mqcomb(Mi, Qi, Mn, Qn);
        }

        // fold boundary element (xin + lane0's T) and finish x
        mqcomb(Mi, Qi, zM, zQ);
        x = S + Mi + lg2f(Qi);

        // post edge carry to stage w+1
        if(w < 7 && lane == 31){
            while(ld_acquire_s32(ack_next) < r - 7){ }
            pay[w][r & 7] = make_float4(u0, u1, x, 0.0f);
            st_release_s32(flag_own, r + 1);
        }

        // tail: head pairs for row r+1 from nx coefs + this row's u/x (off-chain)
        float d0 = __shfl_up_sync(0xffffffffu, u0, 1);
        float d1 = __shfl_up_sync(0xffffffffu, u1, 1);
        float xd = __shfl_up_sync(0xffffffffu, x,  1);
        d0    = lane ? d0 : u0in;
        d1    = lane ? d1 : u1in;
        dlate = lane ? xd : xin;
        P0 = lse2(fmaf(nx.a0, INVLN2, d0), fmaf(nx.a1, INVLN2, d1));
        P1 = lse2(fmaf(nx.a3, INVLN2, u0), fmaf(nx.a4, INVLN2, u1));
        pv2 = x;
        cur = nx;
    };

    for(int r = 0; r < N; r += 2){
        body(r,     nxA, nxB);
        body(r + 1, nxB, nxA);
    }

    // terminal logsumexp at grid cell (N, M) = col 255 = warp 7 lane 31
    if(w == 7 && lane == 31) out[b] = LN2 * lse3(u0, u1, x);
}

extern "C" void kernel_launch(void* const* d_in, const int* in_sizes, int n_in,
                              void* d_out, int out_size) {
    const float* theta = (const float*)d_in[0];
    const float* A     = (const float*)d_in[1];
    // d_in[2] = pos: fixed [(-1,-1),(-1,0),(0,-1)] -> (diag, up, left), hard-coded.
    float* out = (float*)d_out;
    int B = out_size;   // 128 batches, one CTA each
    forward_decoder_kernel<<<B, 256>>>(theta, A, out);
}